// round 1
// baseline (speedup 1.0000x reference)
#include <cuda_runtime.h>
#include <math.h>

#define BSZ 1024
#define NN  100
#define HH  128
#define MTOT (BSZ * NN)   // 102400

// ---------------- scratch (no allocs allowed) ----------------
__device__ float g_h0[(size_t)MTOT * HH];        // hidden0 (gathered embedding)
__device__ float g_ein[(size_t)MTOT * HH];       // e_in
__device__ float g_eout[(size_t)MTOT * HH];      // e_out
__device__ float g_inp[(size_t)MTOT * 2 * HH];   // [input_in | input_out]
__device__ float g_gi[(size_t)MTOT * 3 * HH];    // gi (reused for highway logits)
__device__ float g_gh[(size_t)MTOT * 3 * HH];    // gh
__device__ float g_hid[(size_t)MTOT * HH];       // hidden (post-GRU, then post-blend)
__device__ float g_star[(size_t)BSZ * HH];       // star node

// ---------------- generic tiled fp32 GEMM ----------------
// C[m,n] = sum_k A[m,k] * (BT ? B[n,k] : B[k,n])  (+ bias[n]) (+ C if ACC)
// batched via blockIdx.z with byte-element strides sAb/sBb/sCb.
template<bool BT, bool ACC>
__global__ __launch_bounds__(256)
void gemm_k(const float* __restrict__ A, long sAb, int lda,
            const float* __restrict__ B, long sBb, int ldb,
            const float* __restrict__ bias,
            float* __restrict__ C, long sCb, int ldc,
            int M, int Nt, int K)
{
    const int BM = 64, BN = 64, BK = 16;
    __shared__ float As[BK][BM];
    __shared__ float Bs[BK][BN];

    int bz = blockIdx.z;
    A += (long)bz * sAb;
    B += (long)bz * sBb;
    C += (long)bz * sCb;

    int m0 = blockIdx.y * BM;
    int n0 = blockIdx.x * BN;
    int tid = threadIdx.x;
    int tx = tid & 15;        // 0..15 -> n
    int ty = tid >> 4;        // 0..15 -> m

    float acc[4][4] = {};

    int arow = tid >> 2;          // 0..63
    int akk  = (tid & 3) * 4;     // 0,4,8,12

    for (int k0 = 0; k0 < K; k0 += BK) {
        // A tile: As[k][m]
        #pragma unroll
        for (int u = 0; u < 4; u++) {
            int r = m0 + arow, k = k0 + akk + u;
            As[akk + u][arow] = (r < M && k < K) ? A[(long)r * lda + k] : 0.f;
        }
        // B tile: Bs[k][n]
        if (BT) {
            #pragma unroll
            for (int u = 0; u < 4; u++) {
                int n = n0 + arow, k = k0 + akk + u;
                Bs[akk + u][arow] = (n < Nt && k < K) ? B[(long)n * ldb + k] : 0.f;
            }
        } else {
            int bn = (tid & 15) * 4;   // 0..60
            int bk = tid >> 4;         // 0..15
            #pragma unroll
            for (int u = 0; u < 4; u++) {
                int n = n0 + bn + u, k = k0 + bk;
                Bs[bk][bn + u] = (n < Nt && k < K) ? B[(long)k * ldb + n] : 0.f;
            }
        }
        __syncthreads();

        #pragma unroll
        for (int kk = 0; kk < BK; kk++) {
            float a[4], b[4];
            #pragma unroll
            for (int u = 0; u < 4; u++) a[u] = As[kk][ty * 4 + u];
            #pragma unroll
            for (int v = 0; v < 4; v++) b[v] = Bs[kk][tx * 4 + v];
            #pragma unroll
            for (int u = 0; u < 4; u++)
                #pragma unroll
                for (int v = 0; v < 4; v++)
                    acc[u][v] += a[u] * b[v];
        }
        __syncthreads();
    }

    #pragma unroll
    for (int u = 0; u < 4; u++) {
        int m = m0 + ty * 4 + u;
        if (m >= M) continue;
        #pragma unroll
        for (int v = 0; v < 4; v++) {
            int n = n0 + tx * 4 + v;
            if (n >= Nt) continue;
            float c = acc[u][v];
            if (bias) c += bias[n];
            if (ACC) c += C[(long)m * ldc + n];
            C[(long)m * ldc + n] = c;
        }
    }
}

// ---------------- elementwise / small kernels ----------------
__global__ void gather_k(const int* __restrict__ inputs,
                         const float* __restrict__ emb,
                         float* __restrict__ h0, long total)
{
    long i = (long)blockIdx.x * blockDim.x + threadIdx.x;
    if (i >= total) return;
    long m = i >> 7;            // row
    int  t = (int)(i & 127);
    h0[i] = emb[(long)inputs[m] * HH + t];
}

__global__ void pool_k(const float* __restrict__ h0,
                       const int* __restrict__ gm,
                       float* __restrict__ star)
{
    int b = blockIdx.x, t = threadIdx.x;
    float s = 0.f, c = 0.f;
    const float* hb = h0 + (long)b * NN * HH;
    const int* gb = gm + b * NN;
    for (int i = 0; i < NN; i++) {
        float g = (float)gb[i];
        s += g * hb[(long)i * HH + t];
        c += g;
    }
    star[b * HH + t] = s / c;
}

__device__ __forceinline__ float sigm(float x) { return 1.f / (1.f + expf(-x)); }

__global__ void gru_k(const float* __restrict__ gi, const float* __restrict__ gh,
                      const float* __restrict__ h0, float* __restrict__ hout,
                      long total)
{
    long i = (long)blockIdx.x * blockDim.x + threadIdx.x;
    if (i >= total) return;
    long m = i >> 7;
    int  j = (int)(i & 127);
    long base = m * (3 * HH);
    float ir = gi[base + j],        hr = gh[base + j];
    float ii = gi[base + HH + j],   hi = gh[base + HH + j];
    float in_ = gi[base + 2*HH + j], hn = gh[base + 2*HH + j];
    float r  = sigm(ir + hr);
    float ig = sigm(ii + hi);
    float ng = tanhf(in_ + r * hn);
    float h  = h0[i];
    hout[i] = ng + ig * (h - ng);
}

// star blend + attention pooling (per batch): hidden -> blended hidden, star -> new star
__global__ void star_k(float* __restrict__ hidden,     // [B,N,H] in/out
                       const int* __restrict__ gm,
                       float* __restrict__ star)       // [B,H] in/out
{
    const float inv_sqrt_h = 0.0883883476483184f;  // 1/sqrt(128)
    int b = blockIdx.x;
    int t = threadIdx.x;          // 128 threads
    int lane = t & 31, warp = t >> 5;

    __shared__ float st[HH];
    __shared__ float w[NN];
    __shared__ float red[HH];

    st[t] = star[(long)b * HH + t];
    __syncthreads();

    // star . star (per-warp redundant compute)
    float ssp = 0.f;
    #pragma unroll
    for (int u = 0; u < 4; u++) { float v = st[lane + 32 * u]; ssp += v * v; }
    #pragma unroll
    for (int off = 16; off > 0; off >>= 1) ssp += __shfl_xor_sync(0xffffffffu, ssp, off);
    float ss = ssp;

    float* hb = hidden + (long)b * NN * HH;

    // each warp handles rows warp, warp+4, ...
    for (int i = warp; i < NN; i += 4) {
        float* hr = hb + (long)i * HH;
        float d = 0.f;
        #pragma unroll
        for (int u = 0; u < 4; u++) d += hr[lane + 32 * u] * st[lane + 32 * u];
        #pragma unroll
        for (int off = 16; off > 0; off >>= 1) d += __shfl_xor_sync(0xffffffffu, d, off);
        float alpha = sigm(d * inv_sqrt_h);
        #pragma unroll
        for (int u = 0; u < 4; u++) {
            int c = lane + 32 * u;
            hr[c] = (1.f - alpha) * hr[c] + alpha * st[c];
        }
        float d2 = (1.f - alpha) * d + alpha * ss;  // hidden2 . star
        if (lane == 0) w[i] = expf(d2) * (float)gm[b * NN + i];
    }
    __syncthreads();

    // sum of weights
    red[t] = (t < NN) ? w[t] : 0.f;
    __syncthreads();
    for (int s = 64; s > 0; s >>= 1) {
        if (t < s) red[t] += red[t + s];
        __syncthreads();
    }
    float S = red[0] + 1e-24f;

    // star_new[t] = sum_i (w[i]/S) * hidden2[b,i,t]
    float acc = 0.f;
    for (int i = 0; i < NN; i++) acc += w[i] * hb[(long)i * HH + t];
    star[(long)b * HH + t] = acc / S;
}

__global__ void highway_out_k(const float* __restrict__ logits,
                              const float* __restrict__ h0,
                              const float* __restrict__ hid,
                              float* __restrict__ out, long total)
{
    long i = (long)blockIdx.x * blockDim.x + threadIdx.x;
    if (i >= total) return;
    float a = sigm(logits[i]);
    out[i] = a * h0[i] + (1.f - a) * hid[i];
}

__global__ void copy_star_k(const float* __restrict__ star, float* __restrict__ out)
{
    int i = blockIdx.x * blockDim.x + threadIdx.x;
    if (i < BSZ * HH) out[i] = star[i];
}

// ---------------- launch ----------------
extern "C" void kernel_launch(void* const* d_in, const int* in_sizes, int n_in,
                              void* d_out, int out_size)
{
    const int*   inputs   = (const int*)d_in[0];
    const float* A        = (const float*)d_in[1];
    const int*   gm       = (const int*)d_in[2];
    const float* emb      = (const float*)d_in[3];
    const float* w_ih     = (const float*)d_in[4];
    const float* w_hh     = (const float*)d_in[5];
    const float* b_ih     = (const float*)d_in[6];
    const float* b_hh     = (const float*)d_in[7];
    const float* b_iah    = (const float*)d_in[8];
    const float* b_oah    = (const float*)d_in[9];
    const float* W_ein    = (const float*)d_in[10];
    const float* b_ein    = (const float*)d_in[11];
    const float* W_eout   = (const float*)d_in[12];
    const float* b_eout   = (const float*)d_in[13];
    const float* W_hn     = (const float*)d_in[14];
    const float* b_hn     = (const float*)d_in[15];
    float* out = (float*)d_out;

    float *h0, *ein, *eout, *inp, *gi, *gh, *hid, *star;
    cudaGetSymbolAddress((void**)&h0,   g_h0);
    cudaGetSymbolAddress((void**)&ein,  g_ein);
    cudaGetSymbolAddress((void**)&eout, g_eout);
    cudaGetSymbolAddress((void**)&inp,  g_inp);
    cudaGetSymbolAddress((void**)&gi,   g_gi);
    cudaGetSymbolAddress((void**)&gh,   g_gh);
    cudaGetSymbolAddress((void**)&hid,  g_hid);
    cudaGetSymbolAddress((void**)&star, g_star);

    const long totBNH = (long)MTOT * HH;  // 13,107,200

    // 1) gather embedding -> hidden0 ; initial star (ave pooling)
    gather_k<<<(unsigned)((totBNH + 255) / 256), 256>>>(inputs, emb, h0, totBNH);
    pool_k<<<BSZ, HH>>>(h0, gm, star);

    // 2) e_in / e_out : [102400,128] @ [128,128]^T + bias
    {
        dim3 grid(HH / 64, MTOT / 64, 1);
        gemm_k<true, false><<<grid, 256>>>(h0, 0, HH, W_ein, 0, HH, b_ein,
                                           ein, 0, HH, MTOT, HH, HH);
        gemm_k<true, false><<<grid, 256>>>(h0, 0, HH, W_eout, 0, HH, b_eout,
                                           eout, 0, HH, MTOT, HH, HH);
    }

    // 3) batched: input_in = A[:, :, :N] @ e_in + b_iah ; input_out similarly
    {
        dim3 grid(HH / 64, (NN + 63) / 64, BSZ);
        gemm_k<false, false><<<grid, 256>>>(A, (long)NN * 2 * NN, 2 * NN,
                                            ein, (long)NN * HH, HH, b_iah,
                                            inp, (long)NN * 2 * HH, 2 * HH,
                                            NN, HH, NN);
        gemm_k<false, false><<<grid, 256>>>(A + NN, (long)NN * 2 * NN, 2 * NN,
                                            eout, (long)NN * HH, HH, b_oah,
                                            inp + HH, (long)NN * 2 * HH, 2 * HH,
                                            NN, HH, NN);
    }

    // 4) gi = inp @ w_ih^T + b_ih ; gh = hidden0 @ w_hh^T + b_hh
    {
        dim3 grid(3 * HH / 64, MTOT / 64, 1);
        gemm_k<true, false><<<grid, 256>>>(inp, 0, 2 * HH, w_ih, 0, 2 * HH, b_ih,
                                           gi, 0, 3 * HH, MTOT, 3 * HH, 2 * HH);
        gemm_k<true, false><<<grid, 256>>>(h0, 0, HH, w_hh, 0, HH, b_hh,
                                           gh, 0, 3 * HH, MTOT, 3 * HH, HH);
    }

    // 5) GRU elementwise -> hidden
    gru_k<<<(unsigned)((totBNH + 255) / 256), 256>>>(gi, gh, h0, hid, totBNH);

    // 6) star blend + attention pooling (updates hid and star in place)
    star_k<<<BSZ, HH>>>(hid, gm, star);

    // 7) highway: logits = [h0|hid] @ W_hn^T + b_hn  (two accumulating GEMMs, reuse gi)
    {
        dim3 grid(HH / 64, MTOT / 64, 1);
        gemm_k<true, false><<<grid, 256>>>(h0, 0, HH, W_hn, 0, 2 * HH, b_hn,
                                           gi, 0, HH, MTOT, HH, HH);
        gemm_k<true, true><<<grid, 256>>>(hid, 0, HH, W_hn + HH, 0, 2 * HH,
                                          (const float*)nullptr,
                                          gi, 0, HH, MTOT, HH, HH);
    }

    // 8) output = a*h0 + (1-a)*hid ; append star
    highway_out_k<<<(unsigned)((totBNH + 255) / 256), 256>>>(gi, h0, hid, out, totBNH);
    copy_star_k<<<(BSZ * HH + 255) / 256, 256>>>(star, out + totBNH);
}

// round 2
// speedup vs baseline: 1.9532x; 1.9532x over previous
#include <cuda_runtime.h>
#include <math.h>
#include <stdint.h>

#define BSZ 1024
#define NN  100
#define HH  128
#define MTOT (BSZ * NN)   // 102400

// ---------------- scratch (no allocs allowed) ----------------
__device__ float g_h0[(size_t)MTOT * HH];        // hidden0
__device__ float g_e[(size_t)MTOT * 2 * HH];     // [e_in | e_out], ld=256
__device__ float g_inp[(size_t)MTOT * 2 * HH];   // [input_in | input_out]
__device__ float g_gi[(size_t)MTOT * 3 * HH];    // gi (reused for highway logits)
__device__ float g_gh[(size_t)MTOT * 3 * HH];    // gh
__device__ float g_hid[(size_t)MTOT * HH];       // hidden
__device__ float g_star[(size_t)BSZ * HH];       // star node

// ---------------- tf32 helpers ----------------
__device__ __forceinline__ float totf(float x) {
    uint32_t u; asm("cvt.rna.tf32.f32 %0, %1;" : "=r"(u) : "f"(x));
    return __uint_as_float(u);
}

__device__ __forceinline__ void mma8(float c[4], float2 a01, float2 a23, float2 b01) {
    asm volatile(
        "mma.sync.aligned.m16n8k8.row.col.f32.tf32.tf32.f32 "
        "{%0,%1,%2,%3},{%4,%5,%6,%7},{%8,%9},{%0,%1,%2,%3};"
        : "+f"(c[0]), "+f"(c[1]), "+f"(c[2]), "+f"(c[3])
        : "r"(__float_as_uint(a01.x)), "r"(__float_as_uint(a01.y)),
          "r"(__float_as_uint(a23.x)), "r"(__float_as_uint(a23.y)),
          "r"(__float_as_uint(b01.x)), "r"(__float_as_uint(b01.y)));
}

// ---------------- tensor-core tf32 GEMM ----------------
// C[m,n] = sum_k A[m,k] * (BT ? B[n,k] : B[k,n]) (+bias) (+C if ACC)
// BM=BN=128, BK=8. 256 thr = 8 warps (4m x 2n), warp tile 32x64.
// B/bias may be split at column nsB/nsb between two arrays (concat weights).
template<bool BT, bool ACC, bool GUARD>
__global__ __launch_bounds__(256, 2)
void tc_gemm(const float* __restrict__ A, long sA, int lda,
             const float* __restrict__ B1, const float* __restrict__ B2, int nsB,
             long sB, int ldb,
             const float* __restrict__ bias1, const float* __restrict__ bias2, int nsb,
             float* __restrict__ C, long sC, int ldc,
             int M, int N, int K)
{
    // k-paired layouts: As2[k][i] = {A[m_lo][k], A[m_lo+8][k]} ; Bs2[kq][n] = {B[kq][n], B[kq+4][n]}
    // row strides padded so consecutive k-rows shift by 8 banks -> conflict-free LDS.64
    __shared__ float2 As2[2][8][68];
    __shared__ float2 Bs2[2][4][132];

    A += (long)blockIdx.z * sA;
    C += (long)blockIdx.z * sC;
    const int m0 = blockIdx.y * 128, n0 = blockIdx.x * 128;
    const int tid = threadIdx.x;
    const int lane = tid & 31, warp = tid >> 5;
    const int wm = warp >> 1, wn = warp & 1;
    const int g = lane >> 2, tig = lane & 3;

    // A global-load mapping: thread -> row = tid/2, k-group = (tid&1)*4
    const int a_row = tid >> 1, a_kg = (tid & 1) << 2;
    const float* Ap = A + (long)(m0 + a_row) * lda + a_kg;
    const int a_idx  = ((a_row >> 4) << 3) + (a_row & 7);
    const int a_half = (a_row >> 3) & 1;

    const float* Bp = B1;
    int b_n = 0, b_kg = 0, b_k = 0, b_n4 = 0;
    if (BT) {
        b_n = tid >> 1; b_kg = (tid & 1) << 2;
        int gn = n0 + b_n;
        const float* Bsel = (gn < nsB) ? (B1 + (long)gn * ldb)
                                       : (B2 + (long)(gn - nsB) * ldb);
        Bp = Bsel + b_kg;
    } else {
        b_k = tid >> 5; b_n4 = (tid & 31) << 2;
        Bp = B1 + (long)blockIdx.z * sB + (long)b_k * ldb + n0 + b_n4;
    }

    float acc[2][8][4] = {};
    float va[4], vb[4];
    const int T = (K + 7) >> 3;

    auto ldg = [&](int k0) {
        if (!GUARD) {
            float4 t = *reinterpret_cast<const float4*>(Ap + k0);
            va[0] = t.x; va[1] = t.y; va[2] = t.z; va[3] = t.w;
            const float* bp = BT ? (Bp + k0) : (Bp + (long)k0 * ldb);
            float4 u = *reinterpret_cast<const float4*>(bp);
            vb[0] = u.x; vb[1] = u.y; vb[2] = u.z; vb[3] = u.w;
        } else {
            bool rok = (m0 + a_row) < M;
            if (rok && (k0 + a_kg + 4) <= K) {
                float4 t = *reinterpret_cast<const float4*>(Ap + k0);
                va[0] = t.x; va[1] = t.y; va[2] = t.z; va[3] = t.w;
            } else {
                #pragma unroll
                for (int j = 0; j < 4; j++)
                    va[j] = (rok && (k0 + a_kg + j) < K) ? Ap[k0 + j] : 0.f;
            }
            if ((k0 + b_k) < K) {   // GUARD only used with !BT
                float4 u = *reinterpret_cast<const float4*>(Bp + (long)k0 * ldb);
                vb[0] = u.x; vb[1] = u.y; vb[2] = u.z; vb[3] = u.w;
            } else {
                vb[0] = vb[1] = vb[2] = vb[3] = 0.f;
            }
        }
    };

    auto sts = [&](int s) {
        #pragma unroll
        for (int j = 0; j < 4; j++) {
            float* d = &As2[s][a_kg + j][a_idx].x;
            d[a_half] = totf(va[j]);
        }
        if (BT) {
            #pragma unroll
            for (int j = 0; j < 4; j++) {
                float* d = &Bs2[s][j][b_n].x;
                d[b_kg >> 2] = totf(vb[j]);
            }
        } else {
            #pragma unroll
            for (int j = 0; j < 4; j++) {
                float* d = &Bs2[s][b_k & 3][b_n4 + j].x;
                d[b_k >> 2] = totf(vb[j]);
            }
        }
    };

    auto comp = [&](int s) {
        float2 a01[2], a23[2], bb[8];
        #pragma unroll
        for (int mt = 0; mt < 2; mt++) {
            int idx = (wm * 2 + mt) * 8 + g;
            a01[mt] = As2[s][tig][idx];
            a23[mt] = As2[s][tig + 4][idx];
        }
        #pragma unroll
        for (int nt = 0; nt < 8; nt++)
            bb[nt] = Bs2[s][tig][wn * 64 + nt * 8 + g];
        #pragma unroll
        for (int mt = 0; mt < 2; mt++)
            #pragma unroll
            for (int nt = 0; nt < 8; nt++)
                mma8(acc[mt][nt], a01[mt], a23[mt], bb[nt]);
    };

    ldg(0); sts(0); __syncthreads();
    for (int t = 0; t < T; t++) {
        if (t + 1 < T) ldg((t + 1) << 3);
        comp(t & 1);
        if (t + 1 < T) { __syncthreads(); sts((t + 1) & 1); __syncthreads(); }
    }

    // epilogue
    #pragma unroll
    for (int mt = 0; mt < 2; mt++) {
        int mrow = m0 + wm * 32 + mt * 16 + g;
        #pragma unroll
        for (int half = 0; half < 2; half++) {
            int m = mrow + half * 8;
            if (GUARD && m >= M) continue;
            #pragma unroll
            for (int nt = 0; nt < 8; nt++) {
                int n = n0 + wn * 64 + nt * 8 + tig * 2;
                float bv0 = 0.f, bv1 = 0.f;
                if (bias1) {
                    bv0 = (n     < nsb) ? bias1[n]     : bias2[n - nsb];
                    bv1 = (n + 1 < nsb) ? bias1[n + 1] : bias2[n + 1 - nsb];
                }
                float v0 = acc[mt][nt][half * 2 + 0] + bv0;
                float v1 = acc[mt][nt][half * 2 + 1] + bv1;
                float2* cp = reinterpret_cast<float2*>(C + (long)m * ldc + n);
                if (ACC) { float2 o = *cp; v0 += o.x; v1 += o.y; }
                *cp = make_float2(v0, v1);
            }
        }
    }
}

// ---------------- elementwise / small kernels ----------------
__global__ void gather_k(const int* __restrict__ inputs,
                         const float* __restrict__ emb,
                         float* __restrict__ h0, long total)
{
    long i = (long)blockIdx.x * blockDim.x + threadIdx.x;
    if (i >= total) return;
    long m = i >> 7;
    int  t = (int)(i & 127);
    h0[i] = emb[(long)inputs[m] * HH + t];
}

__global__ void pool_k(const float* __restrict__ h0,
                       const int* __restrict__ gm,
                       float* __restrict__ star)
{
    int b = blockIdx.x, t = threadIdx.x;
    float s = 0.f, c = 0.f;
    const float* hb = h0 + (long)b * NN * HH;
    const int* gb = gm + b * NN;
    for (int i = 0; i < NN; i++) {
        float gmask = (float)gb[i];
        s += gmask * hb[(long)i * HH + t];
        c += gmask;
    }
    star[b * HH + t] = s / c;
}

__device__ __forceinline__ float sigm(float x) { return 1.f / (1.f + expf(-x)); }

__global__ void gru_k(const float* __restrict__ gi, const float* __restrict__ gh,
                      const float* __restrict__ h0, float* __restrict__ hout,
                      long total)
{
    long i = (long)blockIdx.x * blockDim.x + threadIdx.x;
    if (i >= total) return;
    long m = i >> 7;
    int  j = (int)(i & 127);
    long base = m * (3 * HH);
    float ir = gi[base + j],         hr = gh[base + j];
    float ii = gi[base + HH + j],    hi = gh[base + HH + j];
    float in_ = gi[base + 2*HH + j], hn = gh[base + 2*HH + j];
    float r  = sigm(ir + hr);
    float ig = sigm(ii + hi);
    float ng = tanhf(in_ + r * hn);
    float h  = h0[i];
    hout[i] = ng + ig * (h - ng);
}

__global__ void star_k(float* __restrict__ hidden,
                       const int* __restrict__ gm,
                       float* __restrict__ star)
{
    const float inv_sqrt_h = 0.0883883476483184f;  // 1/sqrt(128)
    int b = blockIdx.x;
    int t = threadIdx.x;
    int lane = t & 31, warp = t >> 5;

    __shared__ float st[HH];
    __shared__ float w[NN];
    __shared__ float red[HH];

    st[t] = star[(long)b * HH + t];
    __syncthreads();

    float ssp = 0.f;
    #pragma unroll
    for (int u = 0; u < 4; u++) { float v = st[lane + 32 * u]; ssp += v * v; }
    #pragma unroll
    for (int off = 16; off > 0; off >>= 1) ssp += __shfl_xor_sync(0xffffffffu, ssp, off);
    float ss = ssp;

    float* hb = hidden + (long)b * NN * HH;

    for (int i = warp; i < NN; i += 4) {
        float* hr = hb + (long)i * HH;
        float d = 0.f;
        #pragma unroll
        for (int u = 0; u < 4; u++) d += hr[lane + 32 * u] * st[lane + 32 * u];
        #pragma unroll
        for (int off = 16; off > 0; off >>= 1) d += __shfl_xor_sync(0xffffffffu, d, off);
        float alpha = sigm(d * inv_sqrt_h);
        #pragma unroll
        for (int u = 0; u < 4; u++) {
            int c = lane + 32 * u;
            hr[c] = (1.f - alpha) * hr[c] + alpha * st[c];
        }
        float d2 = (1.f - alpha) * d + alpha * ss;
        if (lane == 0) w[i] = expf(d2) * (float)gm[b * NN + i];
    }
    __syncthreads();

    red[t] = (t < NN) ? w[t] : 0.f;
    __syncthreads();
    for (int s = 64; s > 0; s >>= 1) {
        if (t < s) red[t] += red[t + s];
        __syncthreads();
    }
    float S = red[0] + 1e-24f;

    float acc = 0.f;
    for (int i = 0; i < NN; i++) acc += w[i] * hb[(long)i * HH + t];
    star[(long)b * HH + t] = acc / S;
}

__global__ void highway_out_k(const float* __restrict__ logits,
                              const float* __restrict__ h0,
                              const float* __restrict__ hid,
                              float* __restrict__ out, long total)
{
    long i = (long)blockIdx.x * blockDim.x + threadIdx.x;
    if (i >= total) return;
    float a = sigm(logits[i]);
    out[i] = a * h0[i] + (1.f - a) * hid[i];
}

__global__ void copy_star_k(const float* __restrict__ star, float* __restrict__ out)
{
    int i = blockIdx.x * blockDim.x + threadIdx.x;
    if (i < BSZ * HH) out[i] = star[i];
}

// ---------------- launch ----------------
extern "C" void kernel_launch(void* const* d_in, const int* in_sizes, int n_in,
                              void* d_out, int out_size)
{
    const int*   inputs = (const int*)d_in[0];
    const float* A      = (const float*)d_in[1];
    const int*   gm     = (const int*)d_in[2];
    const float* emb    = (const float*)d_in[3];
    const float* w_ih   = (const float*)d_in[4];
    const float* w_hh   = (const float*)d_in[5];
    const float* b_ih   = (const float*)d_in[6];
    const float* b_hh   = (const float*)d_in[7];
    const float* b_iah  = (const float*)d_in[8];
    const float* b_oah  = (const float*)d_in[9];
    const float* W_ein  = (const float*)d_in[10];
    const float* b_ein  = (const float*)d_in[11];
    const float* W_eout = (const float*)d_in[12];
    const float* b_eout = (const float*)d_in[13];
    const float* W_hn   = (const float*)d_in[14];
    const float* b_hn   = (const float*)d_in[15];
    float* out = (float*)d_out;

    float *h0, *e, *inp, *gi, *gh, *hid, *star;
    cudaGetSymbolAddress((void**)&h0,   g_h0);
    cudaGetSymbolAddress((void**)&e,    g_e);
    cudaGetSymbolAddress((void**)&inp,  g_inp);
    cudaGetSymbolAddress((void**)&gi,   g_gi);
    cudaGetSymbolAddress((void**)&gh,   g_gh);
    cudaGetSymbolAddress((void**)&hid,  g_hid);
    cudaGetSymbolAddress((void**)&star, g_star);

    const long totBNH = (long)MTOT * HH;

    // 1) gather + initial star
    gather_k<<<(unsigned)((totBNH + 255) / 256), 256>>>(inputs, emb, h0, totBNH);
    pool_k<<<BSZ, HH>>>(h0, gm, star);

    // 2) e = [h0 @ W_ein^T + b_ein | h0 @ W_eout^T + b_eout]   (N=256 fused)
    tc_gemm<true, false, false><<<dim3(2, MTOT / 128, 1), 256>>>(
        h0, 0, HH,
        W_ein, W_eout, HH, 0, HH,
        b_ein, b_eout, HH,
        e, 0, 2 * HH,
        MTOT, 2 * HH, HH);

    // 3) batched adjacency GEMMs (M=100, N=128, K=100, guarded)
    tc_gemm<false, false, true><<<dim3(1, 1, BSZ), 256>>>(
        A, (long)NN * 2 * NN, 2 * NN,
        e, e, 2 * HH, (long)NN * 2 * HH, 2 * HH,
        b_iah, b_iah, 2 * HH,
        inp, (long)NN * 2 * HH, 2 * HH,
        NN, HH, NN);
    tc_gemm<false, false, true><<<dim3(1, 1, BSZ), 256>>>(
        A + NN, (long)NN * 2 * NN, 2 * NN,
        e + HH, e + HH, 2 * HH, (long)NN * 2 * HH, 2 * HH,
        b_oah, b_oah, 2 * HH,
        inp + HH, (long)NN * 2 * HH, 2 * HH,
        NN, HH, NN);

    // 4) gi = inp @ w_ih^T + b_ih ; gh = h0 @ w_hh^T + b_hh
    tc_gemm<true, false, false><<<dim3(3, MTOT / 128, 1), 256>>>(
        inp, 0, 2 * HH,
        w_ih, w_ih, 3 * HH, 0, 2 * HH,
        b_ih, b_ih, 3 * HH,
        gi, 0, 3 * HH,
        MTOT, 3 * HH, 2 * HH);
    tc_gemm<true, false, false><<<dim3(3, MTOT / 128, 1), 256>>>(
        h0, 0, HH,
        w_hh, w_hh, 3 * HH, 0, HH,
        b_hh, b_hh, 3 * HH,
        gh, 0, 3 * HH,
        MTOT, 3 * HH, HH);

    // 5) GRU elementwise
    gru_k<<<(unsigned)((totBNH + 255) / 256), 256>>>(gi, gh, h0, hid, totBNH);

    // 6) star blend + attention pooling
    star_k<<<BSZ, HH>>>(hid, gm, star);

    // 7) highway logits = h0 @ W_hn[:, :128]^T + hid @ W_hn[:, 128:]^T + b_hn
    tc_gemm<true, false, false><<<dim3(1, MTOT / 128, 1), 256>>>(
        h0, 0, HH,
        W_hn, W_hn, HH, 0, 2 * HH,
        b_hn, b_hn, HH,
        gi, 0, HH,
        MTOT, HH, HH);
    tc_gemm<true, true, false><<<dim3(1, MTOT / 128, 1), 256>>>(
        hid, 0, HH,
        W_hn + HH, W_hn + HH, HH, 0, 2 * HH,
        (const float*)nullptr, (const float*)nullptr, HH,
        gi, 0, HH,
        MTOT, HH, HH);

    // 8) final blend + star out
    highway_out_k<<<(unsigned)((totBNH + 255) / 256), 256>>>(gi, h0, hid, out, totBNH);
    copy_star_k<<<(BSZ * HH + 255) / 256, 256>>>(star, out + totBNH);
}

// round 4
// speedup vs baseline: 3.1073x; 1.5909x over previous
#include <cuda_runtime.h>
#include <math.h>
#include <stdint.h>

#define BSZ 1024
#define NN  100
#define HH  128
#define MTOT (BSZ * NN)   // 102400

// ---------------- scratch (no allocs allowed) ----------------
__device__ float g_h0[(size_t)MTOT * HH];        // hidden0
__device__ float g_e[(size_t)MTOT * 2 * HH];     // [e_in | e_out], ld=256
__device__ float g_inp[(size_t)MTOT * 2 * HH];   // [input_in | input_out]
__device__ float g_gi[(size_t)MTOT * 3 * HH];    // gi
__device__ float g_gh[(size_t)MTOT * 3 * HH];    // gh
__device__ float g_hid[(size_t)MTOT * HH];       // hidden
__device__ float g_star[(size_t)BSZ * HH];       // star node

// ---------------- tf32 helpers ----------------
__device__ __forceinline__ float totf(float x) {
    uint32_t u; asm("cvt.rna.tf32.f32 %0, %1;" : "=r"(u) : "f"(x));
    return __uint_as_float(u);
}
__device__ __forceinline__ float sigm(float x) { return 1.f / (1.f + expf(-x)); }

__device__ __forceinline__ void mma8(float c[4], float2 a01, float2 a23, float2 b01) {
    asm volatile(
        "mma.sync.aligned.m16n8k8.row.col.f32.tf32.tf32.f32 "
        "{%0,%1,%2,%3},{%4,%5,%6,%7},{%8,%9},{%0,%1,%2,%3};"
        : "+f"(c[0]), "+f"(c[1]), "+f"(c[2]), "+f"(c[3])
        : "r"(__float_as_uint(a01.x)), "r"(__float_as_uint(a01.y)),
          "r"(__float_as_uint(a23.x)), "r"(__float_as_uint(a23.y)),
          "r"(__float_as_uint(b01.x)), "r"(__float_as_uint(b01.y)));
}

// ---------------- tensor-core tf32 GEMM, BK=16, 1 barrier / K-step ----------------
// C[m,n] = sum_k Asel[m,k] * (BT ? B[n,k] : B[k,n]) + bias
// Asel = (SPLITK && k>=ksplit) ? A2 : A1  (both lda)
// EPI: 0 = plain store, 1 = highway blend: a=sigm(v+bias); C = a*A1 + (1-a)*A2 at (m,n)
template<bool BT, bool GUARD, int EPI, bool SPLITK>
__global__ __launch_bounds__(256, 2)
void tc_gemm(const float* __restrict__ A1, const float* __restrict__ A2,
             long sA, int lda, int ksplit,
             const float* __restrict__ B1, const float* __restrict__ B2, int nsB,
             long sB, int ldb,
             const float* __restrict__ bias1, const float* __restrict__ bias2, int nsb,
             float* __restrict__ C, long sC, int ldc,
             int M, int N, int K)
{
    // k-paired layouts: As2[k][i] = {A[m_lo][k], A[m_lo+8][k]}
    // Bs2[(k>>3)*4 + (k&3)][n], half (k>>2)&1 = {B[k8][n], B[k8+4][n]} pairs
    __shared__ float2 As2[2][16][68];
    __shared__ float2 Bs2[2][8][132];

    A1 += (long)blockIdx.z * sA;
    C  += (long)blockIdx.z * sC;
    const int m0 = blockIdx.y * 128, n0 = blockIdx.x * 128;
    const int tid = threadIdx.x;
    const int lane = tid & 31, warp = tid >> 5;
    const int wm = warp >> 1, wn = warp & 1;
    const int g = lane >> 2, tig = lane & 3;

    // A load mapping: row = tid/2, kg = (tid&1)*8
    const int a_row = tid >> 1, a_kg = (tid & 1) << 3;
    const float* pA1 = A1 + (long)(m0 + a_row) * lda + a_kg;
    const float* pA2 = SPLITK ? (A2 + (long)(m0 + a_row) * lda + a_kg) : pA1;
    const int a_idx  = ((a_row >> 4) << 3) + (a_row & 7);
    const int a_half = (a_row >> 3) & 1;

    const float* Bp = B1;
    int b_n = 0, b_kg = 0, b_k = 0, b_n8 = 0;
    if (BT) {
        b_n = tid >> 1; b_kg = (tid & 1) << 3;
        int gn = n0 + b_n;
        const float* Bsel = (gn < nsB) ? (B1 + (long)gn * ldb)
                                       : (B2 + (long)(gn - nsB) * ldb);
        Bp = Bsel + b_kg;
    } else {
        b_k = tid >> 4;              // 0..15
        b_n8 = (tid & 15) << 3;      // 0..120
        Bp = B1 + (long)blockIdx.z * sB + (long)b_k * ldb + n0 + b_n8;
    }

    float acc[2][8][4] = {};
    __align__(16) float va[8];
    __align__(16) float vb[8];
    const int T = (K + 15) >> 4;

    auto ldg = [&](int k0) {
        // ---- A ----
        if (!GUARD) {
            const float* p;
            if (SPLITK) {
                int kk = k0 + a_kg;
                p = (kk < ksplit) ? (pA1 + k0) : (pA2 + (k0 - ksplit));
            } else {
                p = pA1 + k0;
            }
            *reinterpret_cast<float4*>(va)     = *reinterpret_cast<const float4*>(p);
            *reinterpret_cast<float4*>(va + 4) = *reinterpret_cast<const float4*>(p + 4);
        } else {
            bool rok = (m0 + a_row) < M;
            if (rok && (k0 + a_kg + 8) <= K) {
                *reinterpret_cast<float4*>(va)     = *reinterpret_cast<const float4*>(pA1 + k0);
                *reinterpret_cast<float4*>(va + 4) = *reinterpret_cast<const float4*>(pA1 + k0 + 4);
            } else {
                #pragma unroll
                for (int j = 0; j < 8; j++)
                    va[j] = (rok && (k0 + a_kg + j) < K) ? pA1[k0 + j] : 0.f;
            }
        }
        // ---- B ----
        if (BT) {
            *reinterpret_cast<float4*>(vb)     = *reinterpret_cast<const float4*>(Bp + k0);
            *reinterpret_cast<float4*>(vb + 4) = *reinterpret_cast<const float4*>(Bp + k0 + 4);
        } else {
            if ((k0 + b_k) < K) {
                const float* bp = Bp + (long)k0 * ldb;
                *reinterpret_cast<float4*>(vb)     = *reinterpret_cast<const float4*>(bp);
                *reinterpret_cast<float4*>(vb + 4) = *reinterpret_cast<const float4*>(bp + 4);
            } else {
                #pragma unroll
                for (int j = 0; j < 8; j++) vb[j] = 0.f;
            }
        }
    };

    auto sts = [&](int s) {
        #pragma unroll
        for (int j = 0; j < 8; j++) {
            float* d = &As2[s][a_kg + j][a_idx].x;
            d[a_half] = totf(va[j]);
        }
        if (BT) {
            #pragma unroll
            for (int j = 0; j < 8; j++) {
                int k = b_kg + j;
                float* d = &Bs2[s][((k >> 3) << 2) + (k & 3)][b_n].x;
                d[(k >> 2) & 1] = totf(vb[j]);
            }
        } else {
            int k = b_k;
            float* drow = &Bs2[s][((k >> 3) << 2) + (k & 3)][b_n8].x;
            int h = (k >> 2) & 1;
            #pragma unroll
            for (int j = 0; j < 8; j++) drow[j * 2 + h] = totf(vb[j]);
        }
    };

    auto comp = [&](int s) {
        #pragma unroll
        for (int ks = 0; ks < 2; ks++) {
            float2 a01[2], a23[2], bb[8];
            #pragma unroll
            for (int mt = 0; mt < 2; mt++) {
                int idx = (wm * 2 + mt) * 8 + g;
                a01[mt] = As2[s][ks * 8 + tig][idx];
                a23[mt] = As2[s][ks * 8 + tig + 4][idx];
            }
            #pragma unroll
            for (int nt = 0; nt < 8; nt++)
                bb[nt] = Bs2[s][ks * 4 + tig][wn * 64 + nt * 8 + g];
            #pragma unroll
            for (int mt = 0; mt < 2; mt++)
                #pragma unroll
                for (int nt = 0; nt < 8; nt++)
                    mma8(acc[mt][nt], a01[mt], a23[mt], bb[nt]);
        }
    };

    ldg(0); sts(0); __syncthreads();
    for (int t = 0; t < T; t++) {
        if (t + 1 < T) ldg((t + 1) << 4);
        comp(t & 1);
        if (t + 1 < T) { sts((t + 1) & 1); __syncthreads(); }
    }

    // ---------------- epilogue ----------------
    #pragma unroll
    for (int mt = 0; mt < 2; mt++) {
        int mrow = m0 + wm * 32 + mt * 16 + g;
        #pragma unroll
        for (int half = 0; half < 2; half++) {
            int m = mrow + half * 8;
            if (GUARD && m >= M) continue;
            #pragma unroll
            for (int nt = 0; nt < 8; nt++) {
                int n = n0 + wn * 64 + nt * 8 + tig * 2;
                float bv0 = 0.f, bv1 = 0.f;
                if (bias1) {
                    bv0 = (n     < nsb) ? bias1[n]     : bias2[n - nsb];
                    bv1 = (n + 1 < nsb) ? bias1[n + 1] : bias2[n + 1 - nsb];
                }
                float v0 = acc[mt][nt][half * 2 + 0] + bv0;
                float v1 = acc[mt][nt][half * 2 + 1] + bv1;
                float2* cp = reinterpret_cast<float2*>(C + (long)m * ldc + n);
                if (EPI == 1) {
                    // highway blend: A1 = h0, A2 = hid at (m, n), lda == ldc
                    float2 hv = *reinterpret_cast<const float2*>(A1 + (long)m * lda + n);
                    float2 dv = *reinterpret_cast<const float2*>(A2 + (long)m * lda + n);
                    float a0 = sigm(v0), a1 = sigm(v1);
                    *cp = make_float2(a0 * hv.x + (1.f - a0) * dv.x,
                                      a1 * hv.y + (1.f - a1) * dv.y);
                } else {
                    *cp = make_float2(v0, v1);
                }
            }
        }
    }
}

// ---------------- elementwise / small kernels ----------------
__global__ void gather_k(const int* __restrict__ inputs,
                         const float4* __restrict__ emb4,
                         float4* __restrict__ h04, long total4)
{
    long i = (long)blockIdx.x * blockDim.x + threadIdx.x;
    if (i >= total4) return;
    long m = i >> 5;            // 32 float4 per row
    int  t = (int)(i & 31);
    h04[i] = emb4[(long)inputs[m] * 32 + t];
}

__global__ void pool_k(const float* __restrict__ h0,
                       const int* __restrict__ gm,
                       float* __restrict__ star)
{
    int b = blockIdx.x, t = threadIdx.x;
    float s = 0.f, c = 0.f;
    const float* hb = h0 + (long)b * NN * HH;
    const int* gb = gm + b * NN;
    for (int i = 0; i < NN; i++) {
        float gmask = (float)gb[i];
        s += gmask * hb[(long)i * HH + t];
        c += gmask;
    }
    star[b * HH + t] = s / c;
}

__global__ void gru_k(const float* __restrict__ gi, const float* __restrict__ gh,
                      const float* __restrict__ h0, float* __restrict__ hout,
                      long total)
{
    long i = (long)blockIdx.x * blockDim.x + threadIdx.x;
    if (i >= total) return;
    long m = i >> 7;
    int  j = (int)(i & 127);
    long base = m * (3 * HH);
    float ir = gi[base + j],         hr = gh[base + j];
    float ii = gi[base + HH + j],    hi = gh[base + HH + j];
    float in_ = gi[base + 2*HH + j], hn = gh[base + 2*HH + j];
    float r  = sigm(ir + hr);
    float ig = sigm(ii + hi);
    float ng = tanhf(in_ + r * hn);
    float h  = h0[i];
    hout[i] = ng + ig * (h - ng);
}

__global__ void star_k(float* __restrict__ hidden,
                       const int* __restrict__ gm,
                       float* __restrict__ star)
{
    const float inv_sqrt_h = 0.0883883476483184f;  // 1/sqrt(128)
    int b = blockIdx.x;
    int t = threadIdx.x;
    int lane = t & 31, warp = t >> 5;

    __shared__ float st[HH];
    __shared__ float w[NN];
    __shared__ float red[HH];

    st[t] = star[(long)b * HH + t];
    __syncthreads();

    float ssp = 0.f;
    #pragma unroll
    for (int u = 0; u < 4; u++) { float v = st[lane + 32 * u]; ssp += v * v; }
    #pragma unroll
    for (int off = 16; off > 0; off >>= 1) ssp += __shfl_xor_sync(0xffffffffu, ssp, off);
    float ss = ssp;

    float* hb = hidden + (long)b * NN * HH;

    for (int i = warp; i < NN; i += 4) {
        float* hr = hb + (long)i * HH;
        float d = 0.f;
        #pragma unroll
        for (int u = 0; u < 4; u++) d += hr[lane + 32 * u] * st[lane + 32 * u];
        #pragma unroll
        for (int off = 16; off > 0; off >>= 1) d += __shfl_xor_sync(0xffffffffu, d, off);
        float alpha = sigm(d * inv_sqrt_h);
        #pragma unroll
        for (int u = 0; u < 4; u++) {
            int c = lane + 32 * u;
            hr[c] = (1.f - alpha) * hr[c] + alpha * st[c];
        }
        float d2 = (1.f - alpha) * d + alpha * ss;
        if (lane == 0) w[i] = expf(d2) * (float)gm[b * NN + i];
    }
    __syncthreads();

    red[t] = (t < NN) ? w[t] : 0.f;
    __syncthreads();
    for (int s = 64; s > 0; s >>= 1) {
        if (t < s) red[t] += red[t + s];
        __syncthreads();
    }
    float S = red[0] + 1e-24f;

    float acc = 0.f;
    for (int i = 0; i < NN; i++) acc += w[i] * hb[(long)i * HH + t];
    star[(long)b * HH + t] = acc / S;
}

__global__ void copy_star_k(const float* __restrict__ star, float* __restrict__ out)
{
    int i = blockIdx.x * blockDim.x + threadIdx.x;
    if (i < BSZ * HH) out[i] = star[i];
}

// ---------------- launch ----------------
extern "C" void kernel_launch(void* const* d_in, const int* in_sizes, int n_in,
                              void* d_out, int out_size)
{
    const int*   inputs = (const int*)d_in[0];
    const float* A      = (const float*)d_in[1];
    const int*   gm     = (const int*)d_in[2];
    const float* emb    = (const float*)d_in[3];
    const float* w_ih   = (const float*)d_in[4];
    const float* w_hh   = (const float*)d_in[5];
    const float* b_ih   = (const float*)d_in[6];
    const float* b_hh   = (const float*)d_in[7];
    const float* b_iah  = (const float*)d_in[8];
    const float* b_oah  = (const float*)d_in[9];
    const float* W_ein  = (const float*)d_in[10];
    const float* b_ein  = (const float*)d_in[11];
    const float* W_eout = (const float*)d_in[12];
    const float* b_eout = (const float*)d_in[13];
    const float* W_hn   = (const float*)d_in[14];
    const float* b_hn   = (const float*)d_in[15];
    float* out = (float*)d_out;

    float *h0, *e, *inp, *gi, *gh, *hid, *star;
    cudaGetSymbolAddress((void**)&h0,   g_h0);
    cudaGetSymbolAddress((void**)&e,    g_e);
    cudaGetSymbolAddress((void**)&inp,  g_inp);
    cudaGetSymbolAddress((void**)&gi,   g_gi);
    cudaGetSymbolAddress((void**)&gh,   g_gh);
    cudaGetSymbolAddress((void**)&hid,  g_hid);
    cudaGetSymbolAddress((void**)&star, g_star);

    const long totBNH = (long)MTOT * HH;
    const int BIG = 1 << 30;

    // 1) gather + initial star
    gather_k<<<(unsigned)((totBNH / 4 + 255) / 256), 256>>>(
        inputs, (const float4*)emb, (float4*)h0, totBNH / 4);
    pool_k<<<BSZ, HH>>>(h0, gm, star);

    // 2) e = [h0 @ W_ein^T + b_ein | h0 @ W_eout^T + b_eout]   (N=256 fused)
    tc_gemm<true, false, 0, false><<<dim3(2, MTOT / 128, 1), 256>>>(
        h0, h0, 0, HH, 0,
        W_ein, W_eout, HH, 0, HH,
        b_ein, b_eout, HH,
        e, 0, 2 * HH,
        MTOT, 2 * HH, HH);

    // 3) batched adjacency GEMMs (M=100, N=128, K=100, guarded)
    tc_gemm<false, true, 0, false><<<dim3(1, 1, BSZ), 256>>>(
        A, A, (long)NN * 2 * NN, 2 * NN, 0,
        e, e, BIG, (long)NN * 2 * HH, 2 * HH,
        b_iah, b_iah, BIG,
        inp, (long)NN * 2 * HH, 2 * HH,
        NN, HH, NN);
    tc_gemm<false, true, 0, false><<<dim3(1, 1, BSZ), 256>>>(
        A + NN, A + NN, (long)NN * 2 * NN, 2 * NN, 0,
        e + HH, e + HH, BIG, (long)NN * 2 * HH, 2 * HH,
        b_oah, b_oah, BIG,
        inp + HH, (long)NN * 2 * HH, 2 * HH,
        NN, HH, NN);

    // 4) gi = inp @ w_ih^T + b_ih ; gh = h0 @ w_hh^T + b_hh
    tc_gemm<true, false, 0, false><<<dim3(3, MTOT / 128, 1), 256>>>(
        inp, inp, 0, 2 * HH, 0,
        w_ih, w_ih, BIG, 0, 2 * HH,
        b_ih, b_ih, BIG,
        gi, 0, 3 * HH,
        MTOT, 3 * HH, 2 * HH);
    tc_gemm<true, false, 0, false><<<dim3(3, MTOT / 128, 1), 256>>>(
        h0, h0, 0, HH, 0,
        w_hh, w_hh, BIG, 0, HH,
        b_hh, b_hh, BIG,
        gh, 0, 3 * HH,
        MTOT, 3 * HH, HH);

    // 5) GRU elementwise
    gru_k<<<(unsigned)((totBNH + 255) / 256), 256>>>(gi, gh, h0, hid, totBNH);

    // 6) star blend + attention pooling
    star_k<<<BSZ, HH>>>(hid, gm, star);

    // 7+8) highway fused: logits = [h0|hid] @ W_hn^T + b_hn (split-K), blend epilogue -> out
    tc_gemm<true, false, 1, true><<<dim3(1, MTOT / 128, 1), 256>>>(
        h0, hid, 0, HH, HH,
        W_hn, W_hn, BIG, 0, 2 * HH,
        b_hn, b_hn, BIG,
        out, 0, HH,
        MTOT, HH, 2 * HH);

    copy_star_k<<<(BSZ * HH + 255) / 256, 256>>>(star, out + totBNH);
}